// round 6
// baseline (speedup 1.0000x reference)
#include <cuda_runtime.h>
#include <cuda_bf16.h>

#define BS   8
#define CH   256
#define TLEN 512
#define PBIN 16
#define SRAT 4

// 4 MB transposed-input scratch: (b, t, c) layout so channel gathers coalesce.
__device__ float g_tr[BS * TLEN * CH];

// ---------------------------------------------------------------------------
// Kernel 1: transpose (b, ch, t) -> (b, t, ch), 32x32 tiles, float4 loads +
// float4 stores, conflict-free smem (pad 33).
// ---------------------------------------------------------------------------
__global__ __launch_bounds__(256) void transpose_kernel(const float* __restrict__ in) {
    __shared__ float tile[32][33];
    const int b  = blockIdx.z;
    const int t0 = blockIdx.x * 32;
    const int c0 = blockIdx.y * 32;
    const int tx = threadIdx.x;          // 0..7  (float4 index)
    const int ty = threadIdx.y;          // 0..31

    const float* inb  = in   + (size_t)b * CH * TLEN;
    float*       outb = g_tr + (size_t)b * TLEN * CH;

    // load: float4 along t  (8 lanes x 16B = 128B per row-quarter)
    const float4 v = *(const float4*)&inb[(size_t)(c0 + ty) * TLEN + (t0 + 4 * tx)];
    tile[ty][4 * tx + 0] = v.x;          // bank (ty + 4tx + j) % 32: conflict-free
    tile[ty][4 * tx + 1] = v.y;
    tile[ty][4 * tx + 2] = v.z;
    tile[ty][4 * tx + 3] = v.w;
    __syncthreads();

    // store: float4 along c
    float4 w;
    w.x = tile[4 * tx + 0][ty];          // bank (4tx + j + ty) % 32: conflict-free
    w.y = tile[4 * tx + 1][ty];
    w.z = tile[4 * tx + 2][ty];
    w.w = tile[4 * tx + 3][ty];
    *(float4*)&outb[(size_t)(t0 + ty) * CH + (c0 + 4 * tx)] = w;
}

// ---------------------------------------------------------------------------
// Kernel 2: one 64-thread block per ROI. Thread owns 4 STRIDE-64 channels
//   {l, l+64, l+128, l+192} so every gather is a scalar LDG.32 whose warp
//   footprint is exactly ONE 128B line (no within-LDG replays). The 3 extra
//   channels are immediate offsets (+256B/+512B/+768B).
//   Staging: scalar STS, bank = l%32 -> conflict-free, row stride 265 floats
//   (9p bank skew) so the drain is <=2-way. Writeback float4 fully coalesced.
// ---------------------------------------------------------------------------
#define STRIDE 265

__global__ __launch_bounds__(64) void roialign_kernel(const float* __restrict__ rois,
                                                      float4* __restrict__ out) {
    const int n = blockIdx.x;
    const int l = threadIdx.x;           // 0..63

    __shared__ uint4 s_desc[PBIN * SRAT];       // 64 sample descriptors
    __shared__ float s_stage[PBIN * STRIDE];    // [p][chan] skewed rows

    // ---- Phase A: per-sample descriptors (thread i == sample i) ----
    {
        const float bf    = __ldg(&rois[n * 3 + 0]);
        const float start = __ldg(&rois[n * 3 + 1]);
        const float end   = __ldg(&rois[n * 3 + 2]);
        const float roi_len = fmaxf(end - start, 1.0f);
        const float bin     = roi_len * (1.0f / (float)PBIN);

        const int p = l >> 2;            // bin
        const int s = l & 3;             // sample
        const float x = start + ((float)p + ((float)s + 0.5f) * 0.25f) * bin;
        const bool valid = (x >= -1.0f) && (x <= (float)TLEN);
        const float xc = fminf(fmaxf(x, 0.0f), (float)(TLEN - 1));
        const int xl = (int)floorf(xc);
        const int xh = min(xl + 1, TLEN - 1);
        const float lx = xc - (float)xl;
        const int b = (int)bf;

        uint4 d;
        d.x = (unsigned)(((b << 9) + xl) << 10);   // byte offset of row xl
        d.y = (unsigned)(((b << 9) + xh) << 10);   // byte offset of row xh
        d.z = __float_as_uint(valid ? (1.0f - lx) : 0.0f);
        d.w = __float_as_uint(valid ? lx : 0.0f);
        s_desc[l] = d;
    }
    __syncthreads();

    // ---- Phase B: one-line scalar gathers, 4 strided channels/thread ----
    const char* base = (const char*)g_tr + l * 4;    // + q*256B per channel

    #pragma unroll 1
    for (int p = 0; p < PBIN; p++) {
        float a0 = 0.0f, a1 = 0.0f, a2 = 0.0f, a3 = 0.0f;
        #pragma unroll
        for (int s = 0; s < SRAT; s++) {
            const uint4 d = s_desc[p * SRAT + s];
            const float wlo = __uint_as_float(d.z);
            const float whi = __uint_as_float(d.w);
            const float* lo = (const float*)(base + d.x);
            const float* hi = (const float*)(base + d.y);
            a0 += lo[0]   * wlo + hi[0]   * whi;     // chan l
            a1 += lo[64]  * wlo + hi[64]  * whi;     // chan l+64
            a2 += lo[128] * wlo + hi[128] * whi;     // chan l+128
            a3 += lo[192] * wlo + hi[192] * whi;     // chan l+192
        }
        float* row = &s_stage[p * STRIDE];
        row[l]       = a0 * 0.25f;       // bank = (9p + l        ) % 32
        row[l + 64]  = a1 * 0.25f;       // all conflict-free per instr
        row[l + 128] = a2 * 0.25f;
        row[l + 192] = a3 * 0.25f;
    }
    __syncthreads();

    // ---- Phase C: coalesced float4 writeback ----
    float4* outn = out + (size_t)n * (CH * PBIN / 4);

    #pragma unroll
    for (int k = 0; k < 16; k++) {
        const int q = l + 64 * k;        // output float4 index (coalesced)
        const int c = q >> 2;            // channel
        const int g = q & 3;             // bin-group
        float4 v;
        v.x = s_stage[(4 * g + 0) * STRIDE + c];   // bank (4g + 9j + c) % 32
        v.y = s_stage[(4 * g + 1) * STRIDE + c];   // <=2-way across the warp
        v.z = s_stage[(4 * g + 2) * STRIDE + c];
        v.w = s_stage[(4 * g + 3) * STRIDE + c];
        outn[q] = v;
    }
}

extern "C" void kernel_launch(void* const* d_in, const int* in_sizes, int n_in,
                              void* d_out, int out_size) {
    const float* input = (const float*)d_in[0];
    const float* rois  = (const float*)d_in[1];
    float4*      out   = (float4*)d_out;

    const int N = in_sizes[1] / 3;       // 2048 ROIs

    dim3 tgrid(TLEN / 32, CH / 32, BS);  // (16, 8, 8)
    dim3 tblk(8, 32);
    transpose_kernel<<<tgrid, tblk>>>(input);

    roialign_kernel<<<N, 64>>>(rois, out);
}

// round 7
// speedup vs baseline: 1.0276x; 1.0276x over previous
#include <cuda_runtime.h>
#include <cuda_bf16.h>

#define BS   8
#define CH   256
#define TLEN 512
#define PBIN 16
#define SRAT 4

// 4 MB transposed-input scratch: (b, t, c) layout so channel gathers coalesce.
__device__ float g_tr[BS * TLEN * CH];

// ---------------------------------------------------------------------------
// Kernel 1: transpose (b, ch, t) -> (b, t, ch), 32x32 tiles, float4 both ways.
// ---------------------------------------------------------------------------
__global__ __launch_bounds__(256) void transpose_kernel(const float* __restrict__ in) {
    __shared__ float tile[32][33];
    const int b  = blockIdx.z;
    const int t0 = blockIdx.x * 32;
    const int c0 = blockIdx.y * 32;
    const int tx = threadIdx.x;          // 0..7  (float4 index)
    const int ty = threadIdx.y;          // 0..31

    const float* inb  = in   + (size_t)b * CH * TLEN;
    float*       outb = g_tr + (size_t)b * TLEN * CH;

    const float4 v = *(const float4*)&inb[(size_t)(c0 + ty) * TLEN + (t0 + 4 * tx)];
    tile[ty][4 * tx + 0] = v.x;
    tile[ty][4 * tx + 1] = v.y;
    tile[ty][4 * tx + 2] = v.z;
    tile[ty][4 * tx + 3] = v.w;
    __syncthreads();

    float4 w;
    w.x = tile[4 * tx + 0][ty];
    w.y = tile[4 * tx + 1][ty];
    w.z = tile[4 * tx + 2][ty];
    w.w = tile[4 * tx + 3][ty];
    *(float4*)&outb[(size_t)(t0 + ty) * CH + (c0 + 4 * tx)] = w;
}

// ---------------------------------------------------------------------------
// Kernel 2: TWO 64-thread blocks per ROI (half the channels each) -> 8192
//   warps of work, and __launch_bounds__(64,24) caps regs at 42 so 24 blocks
//   (48 warps) are resident per SM. Thread owns 2 stride-64 channels; every
//   gather is a one-line scalar LDG.32 (2nd channel is a +256B immediate).
//   Stage stride 130 floats: STS banks (2p+l)%32 and drain banks (8g+a)%32
//   are conflict-free. Writeback: contiguous float4 range per half-ROI.
// ---------------------------------------------------------------------------
#define S2 130

__global__ __launch_bounds__(64, 24) void roialign_kernel(const float* __restrict__ rois,
                                                          float4* __restrict__ out) {
    const int half = blockIdx.x & 1;         // which 128-channel half
    const int n    = blockIdx.x >> 1;        // ROI index
    const int l    = threadIdx.x;            // 0..63

    __shared__ uint4 s_desc[PBIN * SRAT];    // 64 sample descriptors
    __shared__ float s_stage[PBIN * S2];     // [p][128 chans] stride-130 rows

    // ---- Phase A: per-sample descriptors (thread i == sample i) ----
    {
        const float bf    = __ldg(&rois[n * 3 + 0]);
        const float start = __ldg(&rois[n * 3 + 1]);
        const float end   = __ldg(&rois[n * 3 + 2]);
        const float roi_len = fmaxf(end - start, 1.0f);
        const float bin     = roi_len * (1.0f / (float)PBIN);

        const int p = l >> 2;                // bin
        const int s = l & 3;                 // sample
        const float x = start + ((float)p + ((float)s + 0.5f) * 0.25f) * bin;
        const bool valid = (x >= -1.0f) && (x <= (float)TLEN);
        const float xc = fminf(fmaxf(x, 0.0f), (float)(TLEN - 1));
        const int xl = (int)floorf(xc);
        const int xh = min(xl + 1, TLEN - 1);
        const float lx = xc - (float)xl;
        const int b = (int)bf;

        uint4 d;
        d.x = (unsigned)(((b << 9) + xl) << 10);   // byte offset of row xl
        d.y = (unsigned)(((b << 9) + xh) << 10);   // byte offset of row xh
        d.z = __float_as_uint(valid ? (1.0f - lx) : 0.0f);
        d.w = __float_as_uint(valid ? lx : 0.0f);
        s_desc[l] = d;
    }
    __syncthreads();

    // ---- Phase B: one-line scalar gathers, 2 strided channels/thread ----
    const char* base = (const char*)g_tr + (half * 128 + l) * 4;

    #pragma unroll 1
    for (int p = 0; p < PBIN; p++) {
        float a0 = 0.0f, a1 = 0.0f;
        #pragma unroll
        for (int s = 0; s < SRAT; s++) {
            const uint4 d = s_desc[p * SRAT + s];
            const float wlo = __uint_as_float(d.z);
            const float whi = __uint_as_float(d.w);
            const float* lo = (const float*)(base + d.x);
            const float* hi = (const float*)(base + d.y);
            a0 += lo[0]  * wlo + hi[0]  * whi;   // chan c0
            a1 += lo[64] * wlo + hi[64] * whi;   // chan c0+64
        }
        float* row = &s_stage[p * S2];
        row[l]      = a0 * 0.25f;                // bank (2p + l) % 32
        row[l + 64] = a1 * 0.25f;                // conflict-free
    }
    __syncthreads();

    // ---- Phase C: coalesced float4 writeback (contiguous half-ROI range) ----
    float4* outn = out + (size_t)n * (CH * PBIN / 4) + half * 512;

    #pragma unroll
    for (int k = 0; k < 8; k++) {
        const int q = l + 64 * k;            // 0..511, coalesced
        const int c = q >> 2;                // channel within half (0..127)
        const int g = q & 3;                 // bin-group
        float4 v;
        v.x = s_stage[(4 * g + 0) * S2 + c]; // banks (8g + (l>>2) + ..) % 32
        v.y = s_stage[(4 * g + 1) * S2 + c]; // distinct across warp
        v.z = s_stage[(4 * g + 2) * S2 + c];
        v.w = s_stage[(4 * g + 3) * S2 + c];
        outn[q] = v;
    }
}

extern "C" void kernel_launch(void* const* d_in, const int* in_sizes, int n_in,
                              void* d_out, int out_size) {
    const float* input = (const float*)d_in[0];
    const float* rois  = (const float*)d_in[1];
    float4*      out   = (float4*)d_out;

    const int N = in_sizes[1] / 3;       // 2048 ROIs

    dim3 tgrid(TLEN / 32, CH / 32, BS);  // (16, 8, 8)
    dim3 tblk(8, 32);
    transpose_kernel<<<tgrid, tblk>>>(input);

    roialign_kernel<<<N * 2, 64>>>(rois, out);
}